// round 3
// baseline (speedup 1.0000x reference)
#include <cuda_runtime.h>
#include <cuda_bf16.h>

#define N_NODES 100000
#define DIM 64

// Scratch (no cudaMalloc allowed): aggregation buffer + global accumulators.
__device__ float g_agg[N_NODES * DIM];
__device__ float g_s[DIM];
__device__ float g_wsum;

// ---------------------------------------------------------------------------
// Kernel 1: zero the aggregation buffer and the global accumulators.
// ---------------------------------------------------------------------------
__global__ void zero_kernel() {
    int idx = blockIdx.x * blockDim.x + threadIdx.x;
    const int n4 = N_NODES * DIM / 4;
    if (idx < n4) {
        ((float4*)g_agg)[idx] = make_float4(0.f, 0.f, 0.f, 0.f);
    }
    if (idx < DIM) g_s[idx] = 0.f;
    if (idx == DIM) g_wsum = 0.f;
}

// ---------------------------------------------------------------------------
// Kernel 2: edge scatter.  agg[dst] += x[src]  (64 floats per edge).
// 16 threads per edge, one float4 each; fire-and-forget red.global.add.v4.f32.
// Indices are int32 (harness downcasts the reference's int64).
// ---------------------------------------------------------------------------
__global__ __launch_bounds__(256) void scatter_kernel(
    const float4* __restrict__ x4,
    const int* __restrict__ src,
    const int* __restrict__ dst,
    int E)
{
    int tid = blockIdx.x * blockDim.x + threadIdx.x;
    int e = tid >> 4;
    int p = tid & 15;
    if (e >= E) return;
    int s = src[e];
    int d = dst[e];
    float4 v = x4[(size_t)s * 16 + p];
    float* ap = g_agg + (size_t)d * 64 + p * 4;
    asm volatile("red.global.add.v4.f32 [%0], {%1,%2,%3,%4};"
                 :: "l"(ap), "f"(v.x), "f"(v.y), "f"(v.z), "f"(v.w)
                 : "memory");
}

// ---------------------------------------------------------------------------
// Kernel 3: per-node  h = ReLU((agg+x) @ W1 + b1), accumulate s += w_n * h
// and wsum += w_n.  W1 cached in smem; each warp handles 4 nodes per pass to
// amortize the W1 shared loads (2 LDS serve 8 FFMAs).
// ---------------------------------------------------------------------------
__global__ __launch_bounds__(256) void mlp_reduce_kernel(
    const float* __restrict__ x,
    const float* __restrict__ W1,
    const float* __restrict__ b1,
    const float* __restrict__ weights)
{
    __shared__ float sW1[64 * 64];      // 16 KB
    __shared__ float sv[8][4][64];      // 8 warps x 4 nodes x 64 feats = 8 KB
    __shared__ float sacc[64];
    __shared__ float swsum;

    int tid = threadIdx.x;
    for (int i = tid; i < 64 * 64; i += 256) sW1[i] = W1[i];
    if (tid < 64) sacc[tid] = 0.f;
    if (tid == 0) swsum = 0.f;
    __syncthreads();

    int warp = tid >> 5;
    int lane = tid & 31;
    float b1a = b1[lane];
    float b1b = b1[lane + 32];

    float acc0 = 0.f, acc1 = 0.f, wacc = 0.f;

    const int nGroups = N_NODES / 4;                // 25000, exact
    int gw = blockIdx.x * 8 + warp;
    int strideW = gridDim.x * 8;

    for (int g = gw; g < nGroups; g += strideW) {
        int n0 = g * 4;
        // load (agg + x) rows for 4 nodes into this warp's smem staging
        #pragma unroll
        for (int j = 0; j < 4; j++) {
            int base = (n0 + j) * 64;
            sv[warp][j][lane]      = g_agg[base + lane]      + x[base + lane];
            sv[warp][j][lane + 32] = g_agg[base + lane + 32] + x[base + lane + 32];
        }
        __syncwarp();

        float y00 = b1a, y01 = b1b;
        float y10 = b1a, y11 = b1b;
        float y20 = b1a, y21 = b1b;
        float y30 = b1a, y31 = b1b;
        #pragma unroll
        for (int k = 0; k < 64; k++) {
            float w0 = sW1[k * 64 + lane];
            float w1 = sW1[k * 64 + lane + 32];
            float v0 = sv[warp][0][k];
            float v1 = sv[warp][1][k];
            float v2 = sv[warp][2][k];
            float v3 = sv[warp][3][k];
            y00 += v0 * w0;  y01 += v0 * w1;
            y10 += v1 * w0;  y11 += v1 * w1;
            y20 += v2 * w0;  y21 += v2 * w1;
            y30 += v3 * w0;  y31 += v3 * w1;
        }
        __syncwarp();

        float wt0 = weights[n0];
        float wt1 = weights[n0 + 1];
        float wt2 = weights[n0 + 2];
        float wt3 = weights[n0 + 3];
        acc0 += wt0 * fmaxf(y00, 0.f) + wt1 * fmaxf(y10, 0.f)
              + wt2 * fmaxf(y20, 0.f) + wt3 * fmaxf(y30, 0.f);
        acc1 += wt0 * fmaxf(y01, 0.f) + wt1 * fmaxf(y11, 0.f)
              + wt2 * fmaxf(y21, 0.f) + wt3 * fmaxf(y31, 0.f);
        if (lane == 0) wacc += wt0 + wt1 + wt2 + wt3;
    }

    // block-level reduction in smem, then one atomic per block per element
    atomicAdd(&sacc[lane], acc0);
    atomicAdd(&sacc[lane + 32], acc1);
    if (lane == 0) atomicAdd(&swsum, wacc);
    __syncthreads();

    if (tid < 64) atomicAdd(&g_s[tid], sacc[tid]);
    if (tid == 64) atomicAdd(&g_wsum, swsum);
}

// ---------------------------------------------------------------------------
// Kernel 4: out = s @ W2 + wsum * b2   (single 64x64 matvec)
// ---------------------------------------------------------------------------
__global__ void final_kernel(const float* __restrict__ W2,
                             const float* __restrict__ b2,
                             float* __restrict__ out)
{
    int j = threadIdx.x;  // 0..63
    float acc = g_wsum * b2[j];
    #pragma unroll
    for (int k = 0; k < 64; k++) {
        acc += g_s[k] * W2[k * 64 + j];
    }
    out[j] = acc;
}

// ---------------------------------------------------------------------------
extern "C" void kernel_launch(void* const* d_in, const int* in_sizes, int n_in,
                              void* d_out, int out_size)
{
    const float* x       = (const float*)d_in[0];
    const int*   eidx    = (const int*)d_in[1];
    const float* weights = (const float*)d_in[2];
    const float* W1      = (const float*)d_in[3];
    const float* b1      = (const float*)d_in[4];
    const float* W2      = (const float*)d_in[5];
    const float* b2      = (const float*)d_in[6];
    float*       out     = (float*)d_out;

    int E = in_sizes[1] / 2;
    const int* src = eidx;
    const int* dst = eidx + E;

    // 1) zero scratch
    {
        int n4 = N_NODES * DIM / 4;
        int blocks = (n4 + 255) / 256;
        zero_kernel<<<blocks, 256>>>();
    }
    // 2) edge scatter
    {
        long long threads = (long long)E * 16;
        int blocks = (int)((threads + 255) / 256);
        scatter_kernel<<<blocks, 256>>>((const float4*)x, src, dst, E);
    }
    // 3) MLP + weighted reduction
    mlp_reduce_kernel<<<296, 256>>>(x, W1, b1, weights);
    // 4) final matvec
    final_kernel<<<1, 64>>>(W2, b2, out);
}

// round 6
// speedup vs baseline: 1.4396x; 1.4396x over previous
#include <cuda_runtime.h>
#include <cuda_fp16.h>
#include <cuda_bf16.h>

#define N_NODES 100000
#define DIM 64

// Scratch (no cudaMalloc): fp16 copies of x and the aggregation buffer.
// Each node row = 64 halves = 128 B = 8 uint4.
__device__ uint4 g_xh4[N_NODES * 8];    // x in fp16
__device__ uint4 g_aggh4[N_NODES * 8];  // agg, initialized to x (GIN eps=0 self term)
__device__ float g_s[DIM];
__device__ float g_wsum;

// ---------------------------------------------------------------------------
// Kernel 1: convert x -> fp16 into g_xh4, seed g_aggh4 = x, zero accumulators.
// One thread per uint4 (8 halves).
// ---------------------------------------------------------------------------
__global__ __launch_bounds__(256) void init_kernel(const float4* __restrict__ x4) {
    int idx = blockIdx.x * blockDim.x + threadIdx.x;
    const int n = N_NODES * 8;
    if (idx < n) {
        float4 a = x4[idx * 2];
        float4 b = x4[idx * 2 + 1];
        __half2 h0 = __float22half2_rn(make_float2(a.x, a.y));
        __half2 h1 = __float22half2_rn(make_float2(a.z, a.w));
        __half2 h2 = __float22half2_rn(make_float2(b.x, b.y));
        __half2 h3 = __float22half2_rn(make_float2(b.z, b.w));
        uint4 v;
        v.x = *(unsigned int*)&h0;
        v.y = *(unsigned int*)&h1;
        v.z = *(unsigned int*)&h2;
        v.w = *(unsigned int*)&h3;
        g_xh4[idx] = v;
        g_aggh4[idx] = v;
    }
    if (idx < DIM) g_s[idx] = 0.f;
    if (idx == DIM) g_wsum = 0.f;
}

// ---------------------------------------------------------------------------
// Kernel 2: edge scatter.  agg[dst] += x[src] in fp16.
// 8 threads per edge, one uint4 (8 halves, 16B) each;
// fire-and-forget red.global.add.noftz.v4.f16x2.
// ---------------------------------------------------------------------------
__global__ __launch_bounds__(256) void scatter_kernel(
    const int* __restrict__ src,
    const int* __restrict__ dst,
    int E)
{
    int tid = blockIdx.x * blockDim.x + threadIdx.x;
    int e = tid >> 3;
    int p = tid & 7;
    if (e >= E) return;
    int s = src[e];
    int d = dst[e];
    uint4 v = g_xh4[(size_t)s * 8 + p];
    const uint4* ap = &g_aggh4[(size_t)d * 8 + p];
    asm volatile("red.global.add.noftz.v4.f16x2 [%0], {%1,%2,%3,%4};"
                 :: "l"(ap), "r"(v.x), "r"(v.y), "r"(v.z), "r"(v.w)
                 : "memory");
}

// ---------------------------------------------------------------------------
// Kernel 3: per-node  h = ReLU(agg @ W1 + b1), accumulate s += w_n * h,
// wsum += w_n.  (agg already contains the +x self term.)
// W1 in smem; each warp processes 4 nodes per pass (2 LDS feed 8 FFMAs).
// ---------------------------------------------------------------------------
__global__ __launch_bounds__(256) void mlp_reduce_kernel(
    const float* __restrict__ W1,
    const float* __restrict__ b1,
    const float* __restrict__ weights)
{
    __shared__ float sW1[64 * 64];      // 16 KB
    __shared__ float sv[8][4][64];      // 8 KB
    __shared__ float sacc[64];
    __shared__ float swsum;

    int tid = threadIdx.x;
    for (int i = tid; i < 64 * 64; i += 256) sW1[i] = W1[i];
    if (tid < 64) sacc[tid] = 0.f;
    if (tid == 0) swsum = 0.f;
    __syncthreads();

    int warp = tid >> 5;
    int lane = tid & 31;
    float b1a = b1[lane];
    float b1b = b1[lane + 32];

    float acc0 = 0.f, acc1 = 0.f, wacc = 0.f;

    const __half2* aggh2 = (const __half2*)g_aggh4;   // 32 half2 per node row

    const int nGroups = N_NODES / 4;                  // 25000, exact
    int gw = blockIdx.x * 8 + warp;
    int strideW = gridDim.x * 8;

    for (int g = gw; g < nGroups; g += strideW) {
        int n0 = g * 4;
        #pragma unroll
        for (int j = 0; j < 4; j++) {
            // row = 32 half2; lane loads elements (2l, 2l+1)
            __half2 h = aggh2[(size_t)(n0 + j) * 32 + lane];
            float2 f = __half22float2(h);
            sv[warp][j][2 * lane]     = f.x;
            sv[warp][j][2 * lane + 1] = f.y;
        }
        __syncwarp();

        float y00 = b1a, y01 = b1b;
        float y10 = b1a, y11 = b1b;
        float y20 = b1a, y21 = b1b;
        float y30 = b1a, y31 = b1b;
        #pragma unroll
        for (int k = 0; k < 64; k++) {
            float w0 = sW1[k * 64 + lane];
            float w1 = sW1[k * 64 + lane + 32];
            float v0 = sv[warp][0][k];
            float v1 = sv[warp][1][k];
            float v2 = sv[warp][2][k];
            float v3 = sv[warp][3][k];
            y00 += v0 * w0;  y01 += v0 * w1;
            y10 += v1 * w0;  y11 += v1 * w1;
            y20 += v2 * w0;  y21 += v2 * w1;
            y30 += v3 * w0;  y31 += v3 * w1;
        }
        __syncwarp();

        float wt0 = weights[n0];
        float wt1 = weights[n0 + 1];
        float wt2 = weights[n0 + 2];
        float wt3 = weights[n0 + 3];
        acc0 += wt0 * fmaxf(y00, 0.f) + wt1 * fmaxf(y10, 0.f)
              + wt2 * fmaxf(y20, 0.f) + wt3 * fmaxf(y30, 0.f);
        acc1 += wt0 * fmaxf(y01, 0.f) + wt1 * fmaxf(y11, 0.f)
              + wt2 * fmaxf(y21, 0.f) + wt3 * fmaxf(y31, 0.f);
        if (lane == 0) wacc += wt0 + wt1 + wt2 + wt3;
    }

    atomicAdd(&sacc[lane], acc0);
    atomicAdd(&sacc[lane + 32], acc1);
    if (lane == 0) atomicAdd(&swsum, wacc);
    __syncthreads();

    if (tid < 64) atomicAdd(&g_s[tid], sacc[tid]);
    if (tid == 64) atomicAdd(&g_wsum, swsum);
}

// ---------------------------------------------------------------------------
// Kernel 4: out = s @ W2 + wsum * b2   (single 64x64 matvec)
// ---------------------------------------------------------------------------
__global__ void final_kernel(const float* __restrict__ W2,
                             const float* __restrict__ b2,
                             float* __restrict__ out)
{
    int j = threadIdx.x;  // 0..63
    float acc = g_wsum * b2[j];
    #pragma unroll
    for (int k = 0; k < 64; k++) {
        acc += g_s[k] * W2[k * 64 + j];
    }
    out[j] = acc;
}

// ---------------------------------------------------------------------------
extern "C" void kernel_launch(void* const* d_in, const int* in_sizes, int n_in,
                              void* d_out, int out_size)
{
    const float* x       = (const float*)d_in[0];
    const int*   eidx    = (const int*)d_in[1];
    const float* weights = (const float*)d_in[2];
    const float* W1      = (const float*)d_in[3];
    const float* b1      = (const float*)d_in[4];
    const float* W2      = (const float*)d_in[5];
    const float* b2      = (const float*)d_in[6];
    float*       out     = (float*)d_out;

    int E = in_sizes[1] / 2;
    const int* src = eidx;
    const int* dst = eidx + E;

    // 1) convert + init scratch
    {
        int n = N_NODES * 8;
        int blocks = (n + 255) / 256;
        init_kernel<<<blocks, 256>>>((const float4*)x);
    }
    // 2) edge scatter (fp16 atomics)
    {
        long long threads = (long long)E * 8;
        int blocks = (int)((threads + 255) / 256);
        scatter_kernel<<<blocks, 256>>>(src, dst, E);
    }
    // 3) MLP + weighted reduction
    mlp_reduce_kernel<<<296, 256>>>(W1, b1, weights);
    // 4) final matvec
    final_kernel<<<1, 64>>>(W2, b2, out);
}